// round 8
// baseline (speedup 1.0000x reference)
#include <cuda_runtime.h>
#include <cstdint>

#define NBMAX 4096
__device__ float g_partial[NBMAX];
__device__ unsigned g_count;

// diamond pseudo-angle in [-2,2], monotone in atan2(cy,cx)
__device__ __forceinline__ float pseudo_angle(float cx, float cy) {
    float den = fabsf(cx) + fabsf(cy);
    den = (den == 0.f) ? 1.f : den;
    return copysignf(1.f - __fdividef(cx, den), cy);
}

// Liang-Barsky clip of segment u + t*dd, t in [0,1], against |x|<=a, |y|<=b.
// ix,iy = 1/ddx, 1/ddy. Returns clamped interval length max(t1-t0, 0).
__device__ __forceinline__ float lb_span(float ux, float uy, float ix, float iy,
                                         float a, float b) {
    float lox = (-a - ux) * ix, hix = (a - ux) * ix;
    float loy = (-b - uy) * iy, hiy = (b - uy) * iy;
    float e0 = fminf(lox, hix), e1 = fmaxf(lox, hix);
    float f0 = fminf(loy, hiy), f1 = fmaxf(loy, hiy);
    float t0 = fmaxf(fmaxf(e0, f0), 0.f);
    float t1 = fminf(fminf(e1, f1), 1.f);
    return fmaxf(t1 - t0, 0.f);
}

__global__ void __launch_bounds__(128, 12) poly_giou_kernel(const float* __restrict__ pred,
                                                            const float* __restrict__ target,
                                                            const float* __restrict__ weight,
                                                            float* __restrict__ out,
                                                            int N, int nblocks) {
    const float dxc[4] = {0.5f, -0.5f, -0.5f, 0.5f};
    const float dyc[4] = {0.5f, 0.5f, -0.5f, -0.5f};

    float acc = 0.f;
    int idx = blockIdx.x * blockDim.x + threadIdx.x;
    if (idx < N) {
        float p0 = pred[5 * idx + 0], p1 = pred[5 * idx + 1];
        float p2 = pred[5 * idx + 2], p3 = pred[5 * idx + 3], p4 = pred[5 * idx + 4];
        float t0_ = target[5 * idx + 0], t1_ = target[5 * idx + 1];
        float t2 = target[5 * idx + 2], t3 = target[5 * idx + 3], t4 = target[5 * idx + 4];
        float w = weight[idx];

        // target frame: target = axis rect [-a,a]x[-b,b]; pred center at d, rotated by dd=p4-t4
        float st, ct, sd, cd;
        __sincosf(t4, &st, &ct);
        __sincosf(p4 - t4, &sd, &cd);
        float rx = p0 - t0_, ry = p1 - t1_;
        float dx = ct * rx + st * ry;
        float dy = -st * rx + ct * ry;
        float a = 0.5f * t2, b = 0.5f * t3;   // target half-extents
        float a2 = 0.5f * p2, b2 = 0.5f * p3; // pred half-extents

        // pred corners in target frame (CCW)
        float qx[4], qy[4];
#pragma unroll
        for (int k = 0; k < 4; k++) {
            float cx = dxc[k] * p2, cy = dyc[k] * p3;
            qx[k] = cx * cd - cy * sd + dx;
            qy[k] = cx * sd + cy * cd + dy;
        }

        float twoI = 0.f;  // 2 * intersection area

        // ---- pred edges clipped by target rect (target frame) ----
        {
            float d0x = -p2 * cd, d0y = -p2 * sd;
            float d1x = p3 * sd, d1y = -p3 * cd;
            float i0x = __fdividef(1.f, d0x), i0y = __fdividef(1.f, d0y);
            float i1x = __fdividef(1.f, d1x), i1y = __fdividef(1.f, d1y);
            float s0 = lb_span(qx[0], qy[0], i0x, i0y, a, b);
            float s1 = lb_span(qx[1], qy[1], i1x, i1y, a, b);
            float s2 = lb_span(qx[2], qy[2], -i0x, -i0y, a, b);
            float s3 = lb_span(qx[3], qy[3], -i1x, -i1y, a, b);
            twoI += s0 * (qx[0] * d0y - qy[0] * d0x);
            twoI += s1 * (qx[1] * d1y - qy[1] * d1x);
            twoI += s2 * (qx[2] * (-d0y) - qy[2] * (-d0x));
            twoI += s3 * (qx[3] * (-d1y) - qy[3] * (-d1x));
        }

        // ---- target edges clipped by pred rect (pred frame) + frame correction ----
        {
            float dpx = -(cd * dx + sd * dy);
            float dpy = sd * dx - cd * dy;
            float ux[4], uy[4];
#pragma unroll
            for (int k = 0; k < 4; k++) {
                float cx = dxc[k] * t2, cy = dyc[k] * t3;
                ux[k] = cd * cx + sd * cy + dpx;
                uy[k] = -sd * cx + cd * cy + dpy;
            }
            float e0x = -t2 * cd, e0y = t2 * sd;
            float e1x = -t3 * sd, e1y = -t3 * cd;
            float j0x = __fdividef(1.f, e0x), j0y = __fdividef(1.f, e0y);
            float j1x = __fdividef(1.f, e1x), j1y = __fdividef(1.f, e1y);
            float s0 = lb_span(ux[0], uy[0], j0x, j0y, a2, b2);
            float s1 = lb_span(ux[1], uy[1], j1x, j1y, a2, b2);
            float s2 = lb_span(ux[2], uy[2], -j0x, -j0y, a2, b2);
            float s3 = lb_span(ux[3], uy[3], -j1x, -j1y, a2, b2);
            twoI += s0 * (ux[0] * e0y - uy[0] * e0x);
            twoI += s1 * (ux[1] * e1y - uy[1] * e1x);
            twoI += s2 * (ux[2] * (-e0y) - uy[2] * (-e0x));
            twoI += s3 * (ux[3] * (-e1y) - uy[3] * (-e1x));
            float sdx = (s0 - s2) * e0x + (s1 - s3) * e1x;
            float sdy = (s0 - s2) * e0y + (s1 - s3) * e1y;
            float rsx = cd * sdx - sd * sdy;
            float rsy = sd * sdx + cd * sdy;
            twoI += dx * rsy - dy * rsx;
        }

        float overlap = fabsf(twoI) * 0.5f;

        // ---- enclose: star polygon of 8 corners about exact centroid (dx/2, dy/2) ----
        float mx = 0.5f * dx, my = 0.5f * dy;
        float vx[8], vy[8], ka[8];
#pragma unroll
        for (int k = 0; k < 4; k++) {
            vx[k] = qx[k] - mx;
            vy[k] = qy[k] - my;
            vx[4 + k] = dxc[k] * t2 - mx;
            vy[4 + k] = dyc[k] * t3 - my;
        }
#pragma unroll
        for (int i = 0; i < 8; i++) ka[i] = pseudo_angle(vx[i], vy[i]);

        // Batcher odd-even merge sort, 19 ascending comparators
#define CE(I, J)                                                   \
        {                                                          \
            bool sw = ka[I] > ka[J];                               \
            float t;                                               \
            t = ka[I]; ka[I] = sw ? ka[J] : ka[I]; ka[J] = sw ? t : ka[J]; \
            t = vx[I]; vx[I] = sw ? vx[J] : vx[I]; vx[J] = sw ? t : vx[J]; \
            t = vy[I]; vy[I] = sw ? vy[J] : vy[I]; vy[J] = sw ? t : vy[J]; \
        }
        CE(0, 1) CE(2, 3) CE(4, 5) CE(6, 7)
        CE(0, 2) CE(1, 3) CE(4, 6) CE(5, 7)
        CE(1, 2) CE(5, 6)
        CE(0, 4) CE(1, 5) CE(2, 6) CE(3, 7)
        CE(2, 4) CE(3, 5)
        CE(1, 2) CE(3, 4) CE(5, 6)
#undef CE

        float es = 0.f;
#pragma unroll
        for (int i = 0; i < 8; i++) {
            int j = (i + 1) & 7;
            es += vx[i] * vy[j] - vy[i] * vx[j];
        }
        float enclose = fabsf(es) * 0.5f;

        float uni = p2 * p3 + t2 * t3 - overlap + 1e-6f;
        float iou = fmaxf(__fdividef(overlap, uni), 1e-6f);
        float giou = iou - __fdividef(enclose - uni, enclose);
        acc = (1.f - giou) * w;
    }

    // deterministic block reduction (4 warps)
    float v = acc;
#pragma unroll
    for (int o = 16; o > 0; o >>= 1) v += __shfl_down_sync(0xFFFFFFFFu, v, o);
    __shared__ float ws[4];
    __shared__ bool is_last;
    int lane = threadIdx.x & 31;
    int wid = threadIdx.x >> 5;
    if (lane == 0) ws[wid] = v;
    __syncthreads();
    if (wid == 0) {
        float t = (lane < 4) ? ws[lane] : 0.f;
        t += __shfl_down_sync(0xFFFFFFFFu, t, 2);
        t += __shfl_down_sync(0xFFFFFFFFu, t, 1);
        if (lane == 0) {
            g_partial[blockIdx.x] = t;
            __threadfence();
            unsigned old = atomicAdd(&g_count, 1u);
            is_last = (old == (unsigned)(nblocks - 1));
        }
    }
    __syncthreads();

    if (is_last) {
        __threadfence();
        // 4 independent accumulator chains to hide DADD latency
        double s0 = 0.0, s1 = 0.0, s2 = 0.0, s3 = 0.0;
        int i = threadIdx.x;
        for (; i + 3 * 128 < nblocks; i += 4 * 128) {
            s0 += (double)g_partial[i];
            s1 += (double)g_partial[i + 128];
            s2 += (double)g_partial[i + 256];
            s3 += (double)g_partial[i + 384];
        }
        for (; i < nblocks; i += 128) s0 += (double)g_partial[i];
        double s = (s0 + s1) + (s2 + s3);
        __shared__ double sh[128];
        sh[threadIdx.x] = s;
        __syncthreads();
#pragma unroll
        for (int o = 64; o > 0; o >>= 1) {
            if (threadIdx.x < o) sh[threadIdx.x] += sh[threadIdx.x + o];
            __syncthreads();
        }
        if (threadIdx.x == 0) {
            out[0] = (float)(sh[0] / (double)N);
            g_count = 0u;  // reset for next graph replay
        }
    }
}

extern "C" void kernel_launch(void* const* d_in, const int* in_sizes, int n_in,
                              void* d_out, int out_size) {
    const float* pred = (const float*)d_in[0];
    const float* target = (const float*)d_in[1];
    const float* weight = (const float*)d_in[2];
    int N = in_sizes[2];

    int threads = 128;
    int blocks = (N + threads - 1) / threads;  // 3907 for N=500000, fits NBMAX
    poly_giou_kernel<<<blocks, threads>>>(pred, target, weight, (float*)d_out, N, blocks);
}

// round 9
// speedup vs baseline: 1.0964x; 1.0964x over previous
#include <cuda_runtime.h>
#include <cstdint>

#define NBMAX 2048
__device__ float g_partial[NBMAX];
__device__ unsigned g_count;

// diamond pseudo-angle in [-2,2], monotone in atan2(cy,cx)
__device__ __forceinline__ float pseudo_angle(float cx, float cy) {
    float den = fabsf(cx) + fabsf(cy);
    den = (den == 0.f) ? 1.f : den;
    return copysignf(1.f - __fdividef(cx, den), cy);
}

// monotone float->unsigned, low 3 bits replaced by index (stable tiebreak)
__device__ __forceinline__ unsigned okey(float pa, int i) {
    int ib = __float_as_int(pa);
    unsigned u = (unsigned)(ib ^ ((ib >> 31) | 0x80000000));
    return (u & 0xFFFFFFF8u) | (unsigned)i;
}

// Liang-Barsky clip of segment u + t*dd, t in [0,1], against |x|<=a, |y|<=b.
// ix,iy = 1/ddx, 1/ddy. Returns clamped interval length max(t1-t0, 0).
__device__ __forceinline__ float lb_span(float ux, float uy, float ix, float iy,
                                         float a, float b) {
    float lox = (-a - ux) * ix, hix = (a - ux) * ix;
    float loy = (-b - uy) * iy, hiy = (b - uy) * iy;
    float e0 = fminf(lox, hix), e1 = fmaxf(lox, hix);
    float f0 = fminf(loy, hiy), f1 = fmaxf(loy, hiy);
    float t0 = fmaxf(fmaxf(e0, f0), 0.f);
    float t1 = fminf(fminf(e1, f1), 1.f);
    return fmaxf(t1 - t0, 0.f);
}

__global__ void __launch_bounds__(256) poly_giou_kernel(const float* __restrict__ pred,
                                                        const float* __restrict__ target,
                                                        const float* __restrict__ weight,
                                                        float* __restrict__ out,
                                                        int N, int nblocks) {
    const float dxc[4] = {0.5f, -0.5f, -0.5f, 0.5f};
    const float dyc[4] = {0.5f, 0.5f, -0.5f, -0.5f};

    __shared__ float2 gbuf[8][256];  // per-thread 8-point gather buffer, [k][tid]

    float acc = 0.f;
    int stride = gridDim.x * blockDim.x;
    for (int idx = blockIdx.x * blockDim.x + threadIdx.x; idx < N; idx += stride) {
        float p0 = pred[5 * idx + 0], p1 = pred[5 * idx + 1];
        float p2 = pred[5 * idx + 2], p3 = pred[5 * idx + 3], p4 = pred[5 * idx + 4];
        float t0_ = target[5 * idx + 0], t1_ = target[5 * idx + 1];
        float t2 = target[5 * idx + 2], t3 = target[5 * idx + 3], t4 = target[5 * idx + 4];

        // target frame: target = axis rect [-a,a]x[-b,b]; pred center at d, rotated by dd=p4-t4
        float st, ct, sd, cd;
        __sincosf(t4, &st, &ct);
        __sincosf(p4 - t4, &sd, &cd);
        float rx = p0 - t0_, ry = p1 - t1_;
        float dx = ct * rx + st * ry;
        float dy = -st * rx + ct * ry;
        float a = 0.5f * t2, b = 0.5f * t3;   // target half-extents
        float a2 = 0.5f * p2, b2 = 0.5f * p3; // pred half-extents

        // shared base reciprocals (6 RCP instead of 8)
        float rcd = __fdividef(1.f, cd), rsd = __fdividef(1.f, sd);
        float rp2 = __fdividef(1.f, p2), rp3 = __fdividef(1.f, p3);
        float rt2 = __fdividef(1.f, t2), rt3 = __fdividef(1.f, t3);

        // pred corners in target frame (CCW)
        float qx[4], qy[4];
#pragma unroll
        for (int k = 0; k < 4; k++) {
            float cx = dxc[k] * p2, cy = dyc[k] * p3;
            qx[k] = cx * cd - cy * sd + dx;
            qy[k] = cx * sd + cy * cd + dy;
        }

        float twoI = 0.f;  // 2 * intersection area

        // ---- pred edges clipped by target rect (target frame) ----
        {
            float d0x = -p2 * cd, d0y = -p2 * sd;
            float d1x = p3 * sd, d1y = -p3 * cd;
            float i0x = -rp2 * rcd, i0y = -rp2 * rsd;   // 1/d0x, 1/d0y
            float i1x = rp3 * rsd, i1y = -rp3 * rcd;    // 1/d1x, 1/d1y
            float s0 = lb_span(qx[0], qy[0], i0x, i0y, a, b);
            float s1 = lb_span(qx[1], qy[1], i1x, i1y, a, b);
            float s2 = lb_span(qx[2], qy[2], -i0x, -i0y, a, b);
            float s3 = lb_span(qx[3], qy[3], -i1x, -i1y, a, b);
            twoI += s0 * (qx[0] * d0y - qy[0] * d0x);
            twoI += s1 * (qx[1] * d1y - qy[1] * d1x);
            twoI += s2 * (qx[2] * (-d0y) - qy[2] * (-d0x));
            twoI += s3 * (qx[3] * (-d1y) - qy[3] * (-d1x));
        }

        // ---- target edges clipped by pred rect (pred frame) + frame correction ----
        {
            float dpx = -(cd * dx + sd * dy);
            float dpy = sd * dx - cd * dy;
            float ux[4], uy[4];
#pragma unroll
            for (int k = 0; k < 4; k++) {
                float cx = dxc[k] * t2, cy = dyc[k] * t3;
                ux[k] = cd * cx + sd * cy + dpx;
                uy[k] = -sd * cx + cd * cy + dpy;
            }
            float e0x = -t2 * cd, e0y = t2 * sd;
            float e1x = -t3 * sd, e1y = -t3 * cd;
            float j0x = -rt2 * rcd, j0y = rt2 * rsd;    // 1/e0x, 1/e0y
            float j1x = -rt3 * rsd, j1y = -rt3 * rcd;   // 1/e1x, 1/e1y
            float s0 = lb_span(ux[0], uy[0], j0x, j0y, a2, b2);
            float s1 = lb_span(ux[1], uy[1], j1x, j1y, a2, b2);
            float s2 = lb_span(ux[2], uy[2], -j0x, -j0y, a2, b2);
            float s3 = lb_span(ux[3], uy[3], -j1x, -j1y, a2, b2);
            twoI += s0 * (ux[0] * e0y - uy[0] * e0x);
            twoI += s1 * (ux[1] * e1y - uy[1] * e1x);
            twoI += s2 * (ux[2] * (-e0y) - uy[2] * (-e0x));
            twoI += s3 * (ux[3] * (-e1y) - uy[3] * (-e1x));
            float sdx = (s0 - s2) * e0x + (s1 - s3) * e1x;
            float sdy = (s0 - s2) * e0y + (s1 - s3) * e1y;
            float rsx = cd * sdx - sd * sdy;
            float rsy = sd * sdx + cd * sdy;
            twoI += dx * rsy - dy * rsx;
        }

        float overlap = fabsf(twoI) * 0.5f;

        // ---- enclose: star polygon of 8 corners about exact centroid (dx/2, dy/2) ----
        float mx = 0.5f * dx, my = 0.5f * dy;
        unsigned kk[8];
#pragma unroll
        for (int k = 0; k < 4; k++) {
            float vx = qx[k] - mx, vy = qy[k] - my;
            gbuf[k][threadIdx.x] = make_float2(vx, vy);
            kk[k] = okey(pseudo_angle(vx, vy), k);
            float wx = dxc[k] * t2 - mx, wy = dyc[k] * t3 - my;
            gbuf[4 + k][threadIdx.x] = make_float2(wx, wy);
            kk[4 + k] = okey(pseudo_angle(wx, wy), 4 + k);
        }

        // Batcher odd-even merge sort of keys only, 19 ascending comparators
#define CE(I, J)                             \
        {                                    \
            unsigned lo = min(kk[I], kk[J]); \
            unsigned hi = max(kk[I], kk[J]); \
            kk[I] = lo; kk[J] = hi;          \
        }
        CE(0, 1) CE(2, 3) CE(4, 5) CE(6, 7)
        CE(0, 2) CE(1, 3) CE(4, 6) CE(5, 7)
        CE(1, 2) CE(5, 6)
        CE(0, 4) CE(1, 5) CE(2, 6) CE(3, 7)
        CE(2, 4) CE(3, 5)
        CE(1, 2) CE(3, 4) CE(5, 6)
#undef CE

        // gather points in sorted order (same-thread STS->LDS, ordered, no syncs)
        float2 sp[8];
#pragma unroll
        for (int i = 0; i < 8; i++) sp[i] = gbuf[kk[i] & 7u][threadIdx.x];
        float es = 0.f;
#pragma unroll
        for (int i = 0; i < 8; i++) {
            int j = (i + 1) & 7;
            es += sp[i].x * sp[j].y - sp[i].y * sp[j].x;  // translation-invariant shoelace
        }
        float enclose = fabsf(es) * 0.5f;

        float uni = p2 * p3 + t2 * t3 - overlap + 1e-6f;
        float iou = fmaxf(__fdividef(overlap, uni), 1e-6f);
        // loss = 1 - giou = 2 - iou - uni/enclose
        float loss = 2.f - iou - __fdividef(uni, enclose);
        acc += loss * weight[idx];
    }

    // deterministic block reduction
    float v = acc;
#pragma unroll
    for (int o = 16; o > 0; o >>= 1) v += __shfl_down_sync(0xFFFFFFFFu, v, o);
    __shared__ float ws[8];
    __shared__ bool is_last;
    int lane = threadIdx.x & 31;
    int wid = threadIdx.x >> 5;
    if (lane == 0) ws[wid] = v;
    __syncthreads();
    if (wid == 0) {
        float t = (lane < 8) ? ws[lane] : 0.f;
#pragma unroll
        for (int o = 4; o > 0; o >>= 1) t += __shfl_down_sync(0xFFFFFFFFu, t, o);
        if (lane == 0) {
            g_partial[blockIdx.x] = t;
            __threadfence();
            unsigned old = atomicAdd(&g_count, 1u);
            is_last = (old == (unsigned)(nblocks - 1));
        }
    }
    __syncthreads();

    if (is_last) {
        __threadfence();
        double s = 0.0;
        for (int i = threadIdx.x; i < nblocks; i += blockDim.x) s += (double)g_partial[i];
        __shared__ double sh[256];
        sh[threadIdx.x] = s;
        __syncthreads();
#pragma unroll
        for (int o = 128; o > 0; o >>= 1) {
            if (threadIdx.x < o) sh[threadIdx.x] += sh[threadIdx.x + o];
            __syncthreads();
        }
        if (threadIdx.x == 0) {
            out[0] = (float)(sh[0] / (double)N);
            g_count = 0u;  // reset for next graph replay
        }
    }
}

extern "C" void kernel_launch(void* const* d_in, const int* in_sizes, int n_in,
                              void* d_out, int out_size) {
    const float* pred = (const float*)d_in[0];
    const float* target = (const float*)d_in[1];
    const float* weight = (const float*)d_in[2];
    int N = in_sizes[2];

    int threads = 256;
    int blocks = (N + threads - 1) / threads;
    if (blocks > NBMAX) blocks = NBMAX;

    poly_giou_kernel<<<blocks, threads>>>(pred, target, weight, (float*)d_out, N, blocks);
}

// round 10
// speedup vs baseline: 1.2133x; 1.1067x over previous
#include <cuda_runtime.h>
#include <cstdint>

#define NBMAX 2048
__device__ float g_partial[NBMAX];
__device__ unsigned g_count;

// diamond pseudo-angle in [-2,2], monotone in atan2(cy,cx)
__device__ __forceinline__ float pseudo_angle(float cx, float cy) {
    float den = fabsf(cx) + fabsf(cy);
    den = (den == 0.f) ? 1.f : den;
    return copysignf(1.f - __fdividef(cx, den), cy);
}

// monotone float->unsigned, low 3 bits replaced by index (stable tiebreak)
__device__ __forceinline__ unsigned okey(float pa, int i) {
    int ib = __float_as_int(pa);
    unsigned u = (unsigned)(ib ^ ((ib >> 31) | 0x80000000));
    return (u & 0xFFFFFFF8u) | (unsigned)i;
}

// Liang-Barsky clip of segment u + t*dd, t in [0,1], against |x|<=a, |y|<=b.
__device__ __forceinline__ float lb_span(float ux, float uy, float ix, float iy,
                                         float a, float b) {
    float lox = (-a - ux) * ix, hix = (a - ux) * ix;
    float loy = (-b - uy) * iy, hiy = (b - uy) * iy;
    float e0 = fminf(lox, hix), e1 = fmaxf(lox, hix);
    float f0 = fminf(loy, hiy), f1 = fmaxf(loy, hiy);
    float t0 = fmaxf(fmaxf(e0, f0), 0.f);
    float t1 = fminf(fminf(e1, f1), 1.f);
    return fmaxf(t1 - t0, 0.f);
}

__global__ void __launch_bounds__(256) poly_giou_kernel(const float* __restrict__ pred,
                                                        const float* __restrict__ target,
                                                        const float* __restrict__ weight,
                                                        float* __restrict__ out,
                                                        int N, int nblocks) {
    const float dxc[4] = {0.5f, -0.5f, -0.5f, 0.5f};
    const float dyc[4] = {0.5f, 0.5f, -0.5f, -0.5f};

    __shared__ float2 gbuf[8][256];  // per-thread 8-point gather buffer, [k][tid]

    float acc = 0.f;
    int stride = gridDim.x * blockDim.x;
    for (int idx = blockIdx.x * blockDim.x + threadIdx.x; idx < N; idx += stride) {
        float p0 = pred[5 * idx + 0], p1 = pred[5 * idx + 1];
        float p2 = pred[5 * idx + 2], p3 = pred[5 * idx + 3], p4 = pred[5 * idx + 4];
        float t0_ = target[5 * idx + 0], t1_ = target[5 * idx + 1];
        float t2 = target[5 * idx + 2], t3 = target[5 * idx + 3], t4 = target[5 * idx + 4];

        // target frame: target = axis rect [-a,a]x[-b,b]; pred center at d, rotated by dd=p4-t4
        float st, ct, sd, cd;
        __sincosf(t4, &st, &ct);
        __sincosf(p4 - t4, &sd, &cd);
        float rx = p0 - t0_, ry = p1 - t1_;
        float dx = ct * rx + st * ry;
        float dy = -st * rx + ct * ry;
        float a = 0.5f * t2, b = 0.5f * t3;   // target half-extents
        float a2 = 0.5f * p2, b2 = 0.5f * p3; // pred half-extents

        // shared base reciprocals (6 RCP instead of 8)
        float rcd = __fdividef(1.f, cd), rsd = __fdividef(1.f, sd);
        float rp2 = __fdividef(1.f, p2), rp3 = __fdividef(1.f, p3);
        float rt2 = __fdividef(1.f, t2), rt3 = __fdividef(1.f, t3);

        // pred corners in target frame (CCW)
        float qx[4], qy[4];
#pragma unroll
        for (int k = 0; k < 4; k++) {
            float cx = dxc[k] * p2, cy = dyc[k] * p3;
            qx[k] = cx * cd - cy * sd + dx;
            qy[k] = cx * sd + cy * cd + dy;
        }

        float twoI = 0.f;  // 2 * intersection area

        // ---- pred edges clipped by target rect (target frame) ----
        {
            float d0x = -p2 * cd, d0y = -p2 * sd;
            float d1x = p3 * sd, d1y = -p3 * cd;
            float i0x = -rp2 * rcd, i0y = -rp2 * rsd;   // 1/d0x, 1/d0y
            float i1x = rp3 * rsd, i1y = -rp3 * rcd;    // 1/d1x, 1/d1y
            float s0 = lb_span(qx[0], qy[0], i0x, i0y, a, b);
            float s1 = lb_span(qx[1], qy[1], i1x, i1y, a, b);
            float s2 = lb_span(qx[2], qy[2], -i0x, -i0y, a, b);
            float s3 = lb_span(qx[3], qy[3], -i1x, -i1y, a, b);
            twoI += s0 * (qx[0] * d0y - qy[0] * d0x);
            twoI += s1 * (qx[1] * d1y - qy[1] * d1x);
            twoI += s2 * (qx[2] * (-d0y) - qy[2] * (-d0x));
            twoI += s3 * (qx[3] * (-d1y) - qy[3] * (-d1x));
        }

        // ---- target edges clipped by pred rect (pred frame) + frame correction ----
        {
            float dpx = -(cd * dx + sd * dy);
            float dpy = sd * dx - cd * dy;
            float ux[4], uy[4];
#pragma unroll
            for (int k = 0; k < 4; k++) {
                float cx = dxc[k] * t2, cy = dyc[k] * t3;
                ux[k] = cd * cx + sd * cy + dpx;
                uy[k] = -sd * cx + cd * cy + dpy;
            }
            float e0x = -t2 * cd, e0y = t2 * sd;
            float e1x = -t3 * sd, e1y = -t3 * cd;
            float j0x = -rt2 * rcd, j0y = rt2 * rsd;    // 1/e0x, 1/e0y
            float j1x = -rt3 * rsd, j1y = -rt3 * rcd;   // 1/e1x, 1/e1y
            float s0 = lb_span(ux[0], uy[0], j0x, j0y, a2, b2);
            float s1 = lb_span(ux[1], uy[1], j1x, j1y, a2, b2);
            float s2 = lb_span(ux[2], uy[2], -j0x, -j0y, a2, b2);
            float s3 = lb_span(ux[3], uy[3], -j1x, -j1y, a2, b2);
            twoI += s0 * (ux[0] * e0y - uy[0] * e0x);
            twoI += s1 * (ux[1] * e1y - uy[1] * e1x);
            twoI += s2 * (ux[2] * (-e0y) - uy[2] * (-e0x));
            twoI += s3 * (ux[3] * (-e1y) - uy[3] * (-e1x));
            float sdx = (s0 - s2) * e0x + (s1 - s3) * e1x;
            float sdy = (s0 - s2) * e0y + (s1 - s3) * e1y;
            float rsx = cd * sdx - sd * sdy;
            float rsy = sd * sdx + cd * sdy;
            twoI += dx * rsy - dy * rsx;
        }

        float overlap = fabsf(twoI) * 0.5f;

        // ---- enclose: star polygon of 8 corners about exact centroid (dx/2, dy/2) ----
        float mx = 0.5f * dx, my = 0.5f * dy;
        unsigned kk[8];
#pragma unroll
        for (int k = 0; k < 4; k++) {
            float vx = qx[k] - mx, vy = qy[k] - my;
            gbuf[k][threadIdx.x] = make_float2(vx, vy);
            kk[k] = okey(pseudo_angle(vx, vy), k);
            float wx = dxc[k] * t2 - mx, wy = dyc[k] * t3 - my;
            gbuf[4 + k][threadIdx.x] = make_float2(wx, wy);
            kk[4 + k] = okey(pseudo_angle(wx, wy), 4 + k);
        }

        // Batcher odd-even merge sort of keys only, 19 ascending comparators
#define CE(I, J)                             \
        {                                    \
            unsigned lo = min(kk[I], kk[J]); \
            unsigned hi = max(kk[I], kk[J]); \
            kk[I] = lo; kk[J] = hi;          \
        }
        CE(0, 1) CE(2, 3) CE(4, 5) CE(6, 7)
        CE(0, 2) CE(1, 3) CE(4, 6) CE(5, 7)
        CE(1, 2) CE(5, 6)
        CE(0, 4) CE(1, 5) CE(2, 6) CE(3, 7)
        CE(2, 4) CE(3, 5)
        CE(1, 2) CE(3, 4) CE(5, 6)
#undef CE

        // gather points in sorted order (same-thread STS->LDS, ordered, no syncs)
        float2 sp[8];
#pragma unroll
        for (int i = 0; i < 8; i++) sp[i] = gbuf[kk[i] & 7u][threadIdx.x];
        float es = 0.f;
#pragma unroll
        for (int i = 0; i < 8; i++) {
            int j = (i + 1) & 7;
            es += sp[i].x * sp[j].y - sp[i].y * sp[j].x;  // translation-invariant shoelace
        }
        float enclose = fabsf(es) * 0.5f;

        float uni = p2 * p3 + t2 * t3 - overlap + 1e-6f;
        float iou = fmaxf(__fdividef(overlap, uni), 1e-6f);
        // loss = 1 - giou = 2 - iou - uni/enclose
        float loss = 2.f - iou - __fdividef(uni, enclose);
        acc += loss * weight[idx];
    }

    // deterministic block reduction
    float v = acc;
#pragma unroll
    for (int o = 16; o > 0; o >>= 1) v += __shfl_down_sync(0xFFFFFFFFu, v, o);
    __shared__ float ws[8];
    __shared__ bool is_last;
    int lane = threadIdx.x & 31;
    int wid = threadIdx.x >> 5;
    if (lane == 0) ws[wid] = v;
    __syncthreads();
    if (wid == 0) {
        float t = (lane < 8) ? ws[lane] : 0.f;
#pragma unroll
        for (int o = 4; o > 0; o >>= 1) t += __shfl_down_sync(0xFFFFFFFFu, t, o);
        if (lane == 0) {
            g_partial[blockIdx.x] = t;
            __threadfence();
            unsigned old = atomicAdd(&g_count, 1u);
            is_last = (old == (unsigned)(nblocks - 1));
        }
    }
    __syncthreads();

    if (is_last) {
        __threadfence();
        double s = 0.0;
        for (int i = threadIdx.x; i < nblocks; i += blockDim.x) s += (double)g_partial[i];
        __shared__ double sh[256];
        sh[threadIdx.x] = s;
        __syncthreads();
#pragma unroll
        for (int o = 128; o > 0; o >>= 1) {
            if (threadIdx.x < o) sh[threadIdx.x] += sh[threadIdx.x + o];
            __syncthreads();
        }
        if (threadIdx.x == 0) {
            out[0] = (float)(sh[0] / (double)N);
            g_count = 0u;  // reset for next graph replay
        }
    }
}

extern "C" void kernel_launch(void* const* d_in, const int* in_sizes, int n_in,
                              void* d_out, int out_size) {
    const float* pred = (const float*)d_in[0];
    const float* target = (const float*)d_in[1];
    const float* weight = (const float*)d_in[2];
    int N = in_sizes[2];

    int threads = 256;
    // persistent single-wave grid: 148 SMs x 5 CTAs/SM (48 regs, 256 thr)
    int blocks = 148 * 5;
    int needed = (N + threads - 1) / threads;
    if (blocks > needed) blocks = needed;
    if (blocks > NBMAX) blocks = NBMAX;

    poly_giou_kernel<<<blocks, threads>>>(pred, target, weight, (float*)d_out, N, blocks);
}

// round 11
// speedup vs baseline: 1.2154x; 1.0017x over previous
#include <cuda_runtime.h>
#include <cstdint>

#define NBMAX 2048
__device__ float g_partial[NBMAX];
__device__ unsigned g_count;

// diamond pseudo-angle in [-2,2], monotone in atan2(cy,cx)
__device__ __forceinline__ float pseudo_angle(float cx, float cy) {
    float den = fabsf(cx) + fabsf(cy);
    den = (den == 0.f) ? 1.f : den;
    return copysignf(1.f - __fdividef(cx, den), cy);
}

// monotone float->unsigned, low 3 bits replaced by index (stable tiebreak)
__device__ __forceinline__ unsigned okey(float pa, int i) {
    int ib = __float_as_int(pa);
    unsigned u = (unsigned)(ib ^ ((ib >> 31) | 0x80000000));
    return (u & 0xFFFFFFF8u) | (unsigned)i;
}

// Liang-Barsky clip of segment u + t*dd, t in [0,1], against |x|<=a, |y|<=b.
__device__ __forceinline__ float lb_span(float ux, float uy, float ix, float iy,
                                         float a, float b) {
    float lox = (-a - ux) * ix, hix = (a - ux) * ix;
    float loy = (-b - uy) * iy, hiy = (b - uy) * iy;
    float e0 = fminf(lox, hix), e1 = fmaxf(lox, hix);
    float f0 = fminf(loy, hiy), f1 = fmaxf(loy, hiy);
    float t0 = fmaxf(fmaxf(e0, f0), 0.f);
    float t1 = fminf(fminf(e1, f1), 1.f);
    return fmaxf(t1 - t0, 0.f);
}

// full per-item loss * weight; gcol selects this item's gather column
__device__ __forceinline__ float item_loss(const float* __restrict__ pred,
                                           const float* __restrict__ target,
                                           const float* __restrict__ weight,
                                           float2 (*gbuf)[512], int gcol, int idx) {
    const float dxc[4] = {0.5f, -0.5f, -0.5f, 0.5f};
    const float dyc[4] = {0.5f, 0.5f, -0.5f, -0.5f};

    float p0 = pred[5 * idx + 0], p1 = pred[5 * idx + 1];
    float p2 = pred[5 * idx + 2], p3 = pred[5 * idx + 3], p4 = pred[5 * idx + 4];
    float t0_ = target[5 * idx + 0], t1_ = target[5 * idx + 1];
    float t2 = target[5 * idx + 2], t3 = target[5 * idx + 3], t4 = target[5 * idx + 4];
    float w = weight[idx];

    float st, ct, sd, cd;
    __sincosf(t4, &st, &ct);
    __sincosf(p4 - t4, &sd, &cd);
    float rx = p0 - t0_, ry = p1 - t1_;
    float dx = ct * rx + st * ry;
    float dy = -st * rx + ct * ry;
    float a = 0.5f * t2, b = 0.5f * t3;
    float a2 = 0.5f * p2, b2 = 0.5f * p3;

    float rcd = __fdividef(1.f, cd), rsd = __fdividef(1.f, sd);
    float rp2 = __fdividef(1.f, p2), rp3 = __fdividef(1.f, p3);
    float rt2 = __fdividef(1.f, t2), rt3 = __fdividef(1.f, t3);

    float qx[4], qy[4];
#pragma unroll
    for (int k = 0; k < 4; k++) {
        float cx = dxc[k] * p2, cy = dyc[k] * p3;
        qx[k] = cx * cd - cy * sd + dx;
        qy[k] = cx * sd + cy * cd + dy;
    }

    float twoI = 0.f;

    {   // pred edges clipped by target rect (target frame)
        float d0x = -p2 * cd, d0y = -p2 * sd;
        float d1x = p3 * sd, d1y = -p3 * cd;
        float i0x = -rp2 * rcd, i0y = -rp2 * rsd;
        float i1x = rp3 * rsd, i1y = -rp3 * rcd;
        float s0 = lb_span(qx[0], qy[0], i0x, i0y, a, b);
        float s1 = lb_span(qx[1], qy[1], i1x, i1y, a, b);
        float s2 = lb_span(qx[2], qy[2], -i0x, -i0y, a, b);
        float s3 = lb_span(qx[3], qy[3], -i1x, -i1y, a, b);
        twoI += s0 * (qx[0] * d0y - qy[0] * d0x);
        twoI += s1 * (qx[1] * d1y - qy[1] * d1x);
        twoI += s2 * (qx[2] * (-d0y) - qy[2] * (-d0x));
        twoI += s3 * (qx[3] * (-d1y) - qy[3] * (-d1x));
    }

    {   // target edges clipped by pred rect (pred frame) + frame correction
        float dpx = -(cd * dx + sd * dy);
        float dpy = sd * dx - cd * dy;
        float ux[4], uy[4];
#pragma unroll
        for (int k = 0; k < 4; k++) {
            float cx = dxc[k] * t2, cy = dyc[k] * t3;
            ux[k] = cd * cx + sd * cy + dpx;
            uy[k] = -sd * cx + cd * cy + dpy;
        }
        float e0x = -t2 * cd, e0y = t2 * sd;
        float e1x = -t3 * sd, e1y = -t3 * cd;
        float j0x = -rt2 * rcd, j0y = rt2 * rsd;
        float j1x = -rt3 * rsd, j1y = -rt3 * rcd;
        float s0 = lb_span(ux[0], uy[0], j0x, j0y, a2, b2);
        float s1 = lb_span(ux[1], uy[1], j1x, j1y, a2, b2);
        float s2 = lb_span(ux[2], uy[2], -j0x, -j0y, a2, b2);
        float s3 = lb_span(ux[3], uy[3], -j1x, -j1y, a2, b2);
        twoI += s0 * (ux[0] * e0y - uy[0] * e0x);
        twoI += s1 * (ux[1] * e1y - uy[1] * e1x);
        twoI += s2 * (ux[2] * (-e0y) - uy[2] * (-e0x));
        twoI += s3 * (ux[3] * (-e1y) - uy[3] * (-e1x));
        float sdx = (s0 - s2) * e0x + (s1 - s3) * e1x;
        float sdy = (s0 - s2) * e0y + (s1 - s3) * e1y;
        float rsx = cd * sdx - sd * sdy;
        float rsy = sd * sdx + cd * sdy;
        twoI += dx * rsy - dy * rsx;
    }

    float overlap = fabsf(twoI) * 0.5f;

    // enclose: star polygon of 8 corners about exact centroid (dx/2, dy/2)
    float mx = 0.5f * dx, my = 0.5f * dy;
    unsigned kk[8];
#pragma unroll
    for (int k = 0; k < 4; k++) {
        float vx = qx[k] - mx, vy = qy[k] - my;
        gbuf[k][gcol] = make_float2(vx, vy);
        kk[k] = okey(pseudo_angle(vx, vy), k);
        float wx = dxc[k] * t2 - mx, wy = dyc[k] * t3 - my;
        gbuf[4 + k][gcol] = make_float2(wx, wy);
        kk[4 + k] = okey(pseudo_angle(wx, wy), 4 + k);
    }

#define CE(I, J)                             \
    {                                        \
        unsigned lo = min(kk[I], kk[J]);     \
        unsigned hi = max(kk[I], kk[J]);     \
        kk[I] = lo; kk[J] = hi;              \
    }
    CE(0, 1) CE(2, 3) CE(4, 5) CE(6, 7)
    CE(0, 2) CE(1, 3) CE(4, 6) CE(5, 7)
    CE(1, 2) CE(5, 6)
    CE(0, 4) CE(1, 5) CE(2, 6) CE(3, 7)
    CE(2, 4) CE(3, 5)
    CE(1, 2) CE(3, 4) CE(5, 6)
#undef CE

    float2 sp[8];
#pragma unroll
    for (int i = 0; i < 8; i++) sp[i] = gbuf[kk[i] & 7u][gcol];
    float es = 0.f;
#pragma unroll
    for (int i = 0; i < 8; i++) {
        int j = (i + 1) & 7;
        es += sp[i].x * sp[j].y - sp[i].y * sp[j].x;
    }
    float enclose = fabsf(es) * 0.5f;

    float uni = p2 * p3 + t2 * t3 - overlap + 1e-6f;
    float iou = fmaxf(__fdividef(overlap, uni), 1e-6f);
    float loss = 2.f - iou - __fdividef(uni, enclose);
    return loss * w;
}

__global__ void __launch_bounds__(256) poly_giou_kernel(const float* __restrict__ pred,
                                                        const float* __restrict__ target,
                                                        const float* __restrict__ weight,
                                                        float* __restrict__ out,
                                                        int N, int nblocks) {
    __shared__ float2 gbuf[8][512];  // two gather columns per thread (2-way ILP)

    float acc = 0.f;
    int stride = gridDim.x * blockDim.x;
    int col0 = threadIdx.x << 1;
    for (int idx = blockIdx.x * blockDim.x + threadIdx.x; idx < N; idx += 2 * stride) {
        int idx2 = idx + stride;
        // two independent item streams; compiler interleaves their latency chains
        float l0 = item_loss(pred, target, weight, gbuf, col0, idx);
        float l1 = (idx2 < N) ? item_loss(pred, target, weight, gbuf, col0 | 1, idx2) : 0.f;
        acc += l0 + l1;
    }

    // deterministic block reduction
    float v = acc;
#pragma unroll
    for (int o = 16; o > 0; o >>= 1) v += __shfl_down_sync(0xFFFFFFFFu, v, o);
    __shared__ float ws[8];
    __shared__ bool is_last;
    int lane = threadIdx.x & 31;
    int wid = threadIdx.x >> 5;
    if (lane == 0) ws[wid] = v;
    __syncthreads();
    if (wid == 0) {
        float t = (lane < 8) ? ws[lane] : 0.f;
#pragma unroll
        for (int o = 4; o > 0; o >>= 1) t += __shfl_down_sync(0xFFFFFFFFu, t, o);
        if (lane == 0) {
            g_partial[blockIdx.x] = t;
            __threadfence();
            unsigned old = atomicAdd(&g_count, 1u);
            is_last = (old == (unsigned)(nblocks - 1));
        }
    }
    __syncthreads();

    if (is_last) {
        __threadfence();
        double s = 0.0;
        for (int i = threadIdx.x; i < nblocks; i += blockDim.x) s += (double)g_partial[i];
        __shared__ double sh[256];
        sh[threadIdx.x] = s;
        __syncthreads();
#pragma unroll
        for (int o = 128; o > 0; o >>= 1) {
            if (threadIdx.x < o) sh[threadIdx.x] += sh[threadIdx.x + o];
            __syncthreads();
        }
        if (threadIdx.x == 0) {
            out[0] = (float)(sh[0] / (double)N);
            g_count = 0u;  // reset for next graph replay
        }
    }
}

extern "C" void kernel_launch(void* const* d_in, const int* in_sizes, int n_in,
                              void* d_out, int out_size) {
    const float* pred = (const float*)d_in[0];
    const float* target = (const float*)d_in[1];
    const float* weight = (const float*)d_in[2];
    int N = in_sizes[2];

    int threads = 256;
    // single resident wave at expected 3 CTAs/SM (higher reg use from 2-way ILP)
    int blocks = 148 * 3;
    int needed = (N + threads - 1) / threads;
    if (blocks > needed) blocks = needed;
    if (blocks > NBMAX) blocks = NBMAX;

    poly_giou_kernel<<<blocks, threads>>>(pred, target, weight, (float*)d_out, N, blocks);
}